// round 1
// baseline (speedup 1.0000x reference)
#include <cuda_runtime.h>
#include <cuda_bf16.h>
#include <math.h>

// ---------------- problem constants ----------------
#define Bb   2
#define Ls   2048
#define Dd   1024
#define Kh   32
#define Hh   32
#define Mm   4
#define Aa   4
#define TOT  2080     // 2*D + K
#define CKc  4
#define HM   128      // H*M
#define CH   128      // scan chunk length
#define NC   16       // Ls / CH

// ---------------- scratch (device globals; no allocs allowed) ----------------
__device__ float g_z[(size_t)Bb * Ls * TOT];       // in_proj+conv input/output (34 MB)
__device__ float g_xval[(size_t)Bb * Ls * Dd];     // 16 MB
__device__ float g_gate[(size_t)Bb * Ls * Dd];     // 16 MB
__device__ float g_pw[(size_t)Bb * Ls * Kh];       // p * time_weight
__device__ float g_yg[(size_t)Bb * Ls * Dd];       // (normed proj) * gate
__device__ float g_csum_re[(size_t)Bb * Kh * NC * HM];
__device__ float g_csum_im[(size_t)Bb * Kh * NC * HM];
__device__ float g_cden[(size_t)Bb * Kh * NC];
__device__ float g_WnRe[HM * Hh];                  // norm_scale-folded W_re
__device__ float g_WnIm[HM * Hh];
__device__ float g_w3[3];                          // softmax(deriv_logits)
__device__ float g_slope[Kh];                      // softplus slopes per head

// ---------------- prep: softmax(deriv_logits), slopes, folded W ----------------
__global__ void prep_kernel(const float* __restrict__ dlog,
                            const float* __restrict__ ns,
                            const float* __restrict__ Wre,
                            const float* __restrict__ Wim,
                            const float* __restrict__ ds,
                            const float* __restrict__ as_)
{
    int t = threadIdx.x;
    if (t == 0) {
        float mx = fmaxf(dlog[0], fmaxf(dlog[1], dlog[2]));
        float e0 = expf(dlog[0] - mx), e1 = expf(dlog[1] - mx), e2 = expf(dlog[2] - mx);
        float inv = 1.f / (e0 + e1 + e2);
        g_w3[0] = e0 * inv; g_w3[1] = e1 * inv; g_w3[2] = e2 * inv;
    }
    if (t < Kh) {
        float xx = (t < Kh - Aa) ? ds[t] : as_[t - (Kh - Aa)];
        g_slope[t] = (xx > 20.f) ? xx : log1pf(expf(xx));   // softplus
    }
    for (int i = t; i < HM * Hh; i += blockDim.x) {
        int c = i / Hh;
        g_WnRe[i] = ns[c] * Wre[i];
        g_WnIm[i] = ns[HM + c] * Wim[i];
    }
}

// ---------------- generic tiled SGEMM: C(MxN) = A(MxK) @ B(KxN), row-major ----------------
// BM=128, BN=128, BK=16, 256 threads, 8x8 per thread. K % 16 == 0 assumed (1024 here).
__global__ __launch_bounds__(256, 2)
void sgemm_kernel(const float* __restrict__ A, const float* __restrict__ B,
                  float* __restrict__ C, int Mdim, int Ndim, int Kdim)
{
    __shared__ float As[16][128];
    __shared__ float Bs[16][128];
    const int n0 = blockIdx.x * 128;
    const int m0 = blockIdx.y * 128;
    const int tid = threadIdx.x;
    const int tx = tid & 15;     // output col group
    const int ty = tid >> 4;     // output row group
    float acc[8][8];
#pragma unroll
    for (int i = 0; i < 8; i++)
#pragma unroll
        for (int j = 0; j < 8; j++) acc[i][j] = 0.f;

    for (int k0 = 0; k0 < Kdim; k0 += 16) {
        // load A tile (128 x 16), store transposed
        {
            int r = tid >> 2;            // 0..63
            int s = (tid & 3) * 4;       // k sub-offset
#pragma unroll
            for (int rr = 0; rr < 2; rr++) {
                int row = r + rr * 64;
                float4 v = make_float4(0.f, 0.f, 0.f, 0.f);
                if (m0 + row < Mdim)
                    v = *reinterpret_cast<const float4*>(&A[(size_t)(m0 + row) * Kdim + k0 + s]);
                As[s + 0][row] = v.x; As[s + 1][row] = v.y;
                As[s + 2][row] = v.z; As[s + 3][row] = v.w;
            }
        }
        // load B tile (16 x 128)
        {
#pragma unroll
            for (int it = 0; it < 2; it++) {
                int idx = tid + it * 256;        // 0..511
                int kr = idx >> 5;               // 0..15
                int nc = (idx & 31) * 4;
                float4 v = make_float4(0.f, 0.f, 0.f, 0.f);
                if (n0 + nc + 3 < Ndim) {
                    v = *reinterpret_cast<const float4*>(&B[(size_t)(k0 + kr) * Ndim + n0 + nc]);
                } else {
                    float tmp[4] = {0.f, 0.f, 0.f, 0.f};
                    for (int j = 0; j < 4; j++)
                        if (n0 + nc + j < Ndim) tmp[j] = B[(size_t)(k0 + kr) * Ndim + n0 + nc + j];
                    v = make_float4(tmp[0], tmp[1], tmp[2], tmp[3]);
                }
                *reinterpret_cast<float4*>(&Bs[kr][nc]) = v;
            }
        }
        __syncthreads();
#pragma unroll
        for (int kk = 0; kk < 16; kk++) {
            float af[8], bf[8];
#pragma unroll
            for (int i = 0; i < 8; i++) af[i] = As[kk][ty * 8 + i];
#pragma unroll
            for (int j = 0; j < 8; j++) bf[j] = Bs[kk][tx * 8 + j];
#pragma unroll
            for (int i = 0; i < 8; i++)
#pragma unroll
                for (int j = 0; j < 8; j++) acc[i][j] += af[i] * bf[j];
        }
        __syncthreads();
    }
#pragma unroll
    for (int i = 0; i < 8; i++) {
        int row = m0 + ty * 8 + i;
        if (row >= Mdim) continue;
#pragma unroll
        for (int j = 0; j < 8; j++) {
            int col = n0 + tx * 8 + j;
            if (col < Ndim) C[(size_t)row * Ndim + col] = acc[i][j];
        }
    }
}

// ---------------- causal depthwise conv + split into xval / gate / p*time_weight ----------------
__global__ void conv_kernel(const float* __restrict__ cw, const float* __restrict__ cb,
                            const float* __restrict__ sscale)
{
    int idx = blockIdx.x * blockDim.x + threadIdx.x;
    if (idx >= Bb * Ls * TOT) return;
    int c  = idx % TOT;
    int bl = idx / TOT;
    int l  = bl % Ls;

    float acc = cb[c];
#pragma unroll
    for (int j = 0; j < CKc; j++) {
        int ll = l - j;
        if (ll >= 0)
            acc += g_z[(size_t)(bl - j) * TOT + c] * cw[(CKc - 1 - j) * TOT + c];
    }
    if (c < Dd) {
        g_xval[(size_t)bl * Dd + c] = acc;
    } else if (c < 2 * Dd) {
        float sg = 1.f / (1.f + expf(-acc));
        g_gate[(size_t)bl * Dd + (c - Dd)] = acc * sg;   // silu
    } else {
        int k = c - 2 * Dd;
        float sr = sscale[k] * acc;
        sr = fminf(20.f, fmaxf(-20.f, sr));
        float p = expf(sr);
        float dist = (k < Kh - Aa) ? (float)(Ls - 1 - l) : (float)l;
        float tw = expf(-g_slope[k] * dist);
        g_pw[(size_t)bl * Kh + k] = p * tw;
    }
}

// ---------------- pass 1: per-(b,k,chunk) partial sums ----------------
__global__ __launch_bounds__(128)
void csum_kernel(const float* __restrict__ theta)
{
    int bi    = blockIdx.x;          // ((b*K + k)*NC + chunk)
    int chunk = bi % NC;
    int bk    = bi / NC;
    int k     = bk % Kh;
    int b     = bk / Kh;
    int c = threadIdx.x;             // channel 0..127
    int h = c >> 2, m = c & 3;
    float th = theta[(k * Hh + h) * Mm + m];
    float w0 = g_w3[0], w1 = g_w3[1], w2 = g_w3[2];

    float are = 0.f, aim = 0.f, ad = 0.f;
    size_t base = ((size_t)b * Ls + chunk * CH);
    const float* xvp = &g_xval[base * Dd + k * Hh + h];
    const float* pwp = &g_pw[base * Kh + k];
    for (int i = 0; i < CH; i++) {
        float xv  = xvp[(size_t)i * Dd];
        float pwv = pwp[(size_t)i * Kh];
        float s, co; __sincosf(xv * th, &s, &co);
        float poly = w0 + xv * (w1 - w2 * xv);
        float t = pwv * poly;
        are += t * co; aim += t * s; ad += pwv;
    }
    g_csum_re[(size_t)bi * HM + c] = are;
    g_csum_im[(size_t)bi * HM + c] = aim;
    if (c == 0) g_cden[bi] = ad;
}

// ---------------- pass 2: exclusive scan over chunks (tiny) ----------------
__global__ __launch_bounds__(128)
void cscan_kernel()
{
    int bk = blockIdx.x;     // 0..B*K-1
    int c = threadIdx.x;
    float rr = 0.f, ri = 0.f;
    for (int ch = 0; ch < NC; ch++) {
        size_t idx = ((size_t)bk * NC + ch) * HM + c;
        float tr = g_csum_re[idx], ti = g_csum_im[idx];
        g_csum_re[idx] = rr; g_csum_im[idx] = ri;
        rr += tr; ri += ti;
    }
    if (c == 0) {
        float run = 0.f;
        for (int ch = 0; ch < NC; ch++) {
            float t = g_cden[bk * NC + ch];
            g_cden[bk * NC + ch] = run;
            run += t;
        }
    }
}

// ---------------- pass 3: within-chunk scan + RMS + head matvec + gate ----------------
__global__ __launch_bounds__(128)
void main_kernel(const float* __restrict__ theta)
{
    __shared__ float WnRe_s[HM * Hh];   // [c][h'] 16 KB
    __shared__ float WnIm_s[HM * Hh];   // 16 KB
    __shared__ float sh_re[HM], sh_im[HM], sh_sq[HM];
    __shared__ float sh_part[HM];
    __shared__ float sh_scale;

    int bi    = blockIdx.x;
    int chunk = bi % NC;
    int bk    = bi / NC;
    int k     = bk % Kh;
    int b     = bk / Kh;
    int c = threadIdx.x;
    int h = c >> 2, m = c & 3;
    int q = c >> 5, hp = c & 31;

    for (int i = c; i < HM * Hh; i += 128) {
        WnRe_s[i] = g_WnRe[i];
        WnIm_s[i] = g_WnIm[i];
    }
    float th = theta[(k * Hh + h) * Mm + m];
    float w0 = g_w3[0], w1 = g_w3[1], w2 = g_w3[2];
    float are = g_csum_re[(size_t)bi * HM + c];
    float aim = g_csum_im[(size_t)bi * HM + c];
    float den = g_cden[bi];             // identical in all threads, tracked redundantly
    __syncthreads();

    int base_l = chunk * CH;
    for (int i = 0; i < CH; i++) {
        int l = base_l + i;
        size_t bl = (size_t)b * Ls + l;
        float xv  = g_xval[bl * Dd + k * Hh + h];
        float pwv = g_pw[bl * Kh + k];
        float s, co; __sincosf(xv * th, &s, &co);
        float poly = w0 + xv * (w1 - w2 * xv);
        float t = pwv * poly;
        are += t * co; aim += t * s; den += pwv;

        sh_re[c] = are; sh_im[c] = aim; sh_sq[c] = are * are + aim * aim;
        __syncthreads();

        // partial matvec: quarter q over 32 channels for output hp
        float part = 0.f;
#pragma unroll
        for (int j = 0; j < 32; j++) {
            int cc = q * 32 + j;
            part += sh_re[cc] * WnRe_s[cc * Hh + hp] + sh_im[cc] * WnIm_s[cc * Hh + hp];
        }
        sh_part[c] = part;

        // warp 0 computes the RMS scale
        if (q == 0) {
            float v = sh_sq[hp] + sh_sq[hp + 32] + sh_sq[hp + 64] + sh_sq[hp + 96];
#pragma unroll
            for (int o = 16; o > 0; o >>= 1) v += __shfl_xor_sync(0xffffffffu, v, o);
            if (hp == 0) {
                float inv_den = 1.f / fmaxf(den, 1e-4f);
                float msq = inv_den * inv_den * v * (1.f / (2.f * HM)) + 1e-5f;
                sh_scale = inv_den * rsqrtf(msq);
            }
        }
        __syncthreads();

        if (c < 32) {
            float y = (sh_part[c] + sh_part[c + 32] + sh_part[c + 64] + sh_part[c + 96]) * sh_scale;
            size_t oidx = bl * Dd + k * Hh + c;
            g_yg[oidx] = y * g_gate[oidx];
        }
        __syncthreads();
    }
}

// ---------------- launcher ----------------
extern "C" void kernel_launch(void* const* d_in, const int* in_sizes, int n_in,
                              void* d_out, int out_size)
{
    const float* x             = (const float*)d_in[0];
    const float* in_proj_w     = (const float*)d_in[1];
    const float* conv_w        = (const float*)d_in[2];
    const float* conv_b        = (const float*)d_in[3];
    const float* theta         = (const float*)d_in[4];
    const float* decay_slopes  = (const float*)d_in[5];
    const float* anchor_slopes = (const float*)d_in[6];
    const float* score_scale   = (const float*)d_in[7];
    const float* deriv_logits  = (const float*)d_in[8];
    const float* norm_scale    = (const float*)d_in[9];
    const float* W_re          = (const float*)d_in[10];
    const float* W_im          = (const float*)d_in[11];
    const float* out_proj_w    = (const float*)d_in[12];
    float* out = (float*)d_out;

    float *z_p = nullptr, *yg_p = nullptr;
    cudaGetSymbolAddress((void**)&z_p, g_z);
    cudaGetSymbolAddress((void**)&yg_p, g_yg);

    prep_kernel<<<1, 256>>>(deriv_logits, norm_scale, W_re, W_im,
                            decay_slopes, anchor_slopes);

    // z = x @ in_proj_w : (4096 x 1024) @ (1024 x 2080)
    sgemm_kernel<<<dim3((TOT + 127) / 128, (Bb * Ls) / 128), 256>>>(
        x, in_proj_w, z_p, Bb * Ls, TOT, Dd);

    conv_kernel<<<(Bb * Ls * TOT + 255) / 256, 256>>>(conv_w, conv_b, score_scale);

    csum_kernel<<<Bb * Kh * NC, 128>>>(theta);
    cscan_kernel<<<Bb * Kh, 128>>>();
    main_kernel<<<Bb * Kh * NC, 128>>>(theta);

    // out = yg @ out_proj_w : (4096 x 1024) @ (1024 x 1024)
    sgemm_kernel<<<dim3(Dd / 128, (Bb * Ls) / 128), 256>>>(
        yg_p, out_proj_w, out, Bb * Ls, Dd, Dd);
}

// round 2
// speedup vs baseline: 1.5415x; 1.5415x over previous
#include <cuda_runtime.h>
#include <cuda_bf16.h>
#include <math.h>

// ---------------- problem constants ----------------
#define Bb   2
#define Ls   2048
#define Dd   1024
#define Kh   32
#define Hh   32
#define Mm   4
#define Aa   4
#define TOT  2080     // 2*D + K
#define CKc  4
#define HM   128      // H*M
#define CH   128      // scan chunk length
#define NC   16       // Ls / CH

// ---------------- scratch (device globals; no allocs allowed) ----------------
__device__ float g_z[(size_t)Bb * Ls * TOT];       // in_proj+conv output (34 MB)
__device__ float g_xval[(size_t)Bb * Ls * Dd];     // 16 MB
__device__ float g_gate[(size_t)Bb * Ls * Dd];     // 16 MB
__device__ float g_pw[(size_t)Bb * Ls * Kh];       // p * time_weight
__device__ float g_yg[(size_t)Bb * Ls * Dd];       // (normed proj) * gate
__device__ float g_csum_re[(size_t)Bb * Kh * NC * HM];
__device__ float g_csum_im[(size_t)Bb * Kh * NC * HM];
__device__ float g_cden[(size_t)Bb * Kh * NC];
__device__ float g_WnRe[HM * Hh];                  // norm_scale-folded W_re
__device__ float g_WnIm[HM * Hh];
__device__ float g_w3[3];                          // softmax(deriv_logits)
__device__ float g_slope[Kh];                      // softplus slopes per head

// ---------------- prep ----------------
__global__ void prep_kernel(const float* __restrict__ dlog,
                            const float* __restrict__ ns,
                            const float* __restrict__ Wre,
                            const float* __restrict__ Wim,
                            const float* __restrict__ ds,
                            const float* __restrict__ as_)
{
    int t = threadIdx.x;
    if (t == 0) {
        float mx = fmaxf(dlog[0], fmaxf(dlog[1], dlog[2]));
        float e0 = expf(dlog[0] - mx), e1 = expf(dlog[1] - mx), e2 = expf(dlog[2] - mx);
        float inv = 1.f / (e0 + e1 + e2);
        g_w3[0] = e0 * inv; g_w3[1] = e1 * inv; g_w3[2] = e2 * inv;
    }
    if (t < Kh) {
        float xx = (t < Kh - Aa) ? ds[t] : as_[t - (Kh - Aa)];
        g_slope[t] = (xx > 20.f) ? xx : log1pf(expf(xx));   // softplus
    }
    for (int i = t; i < HM * Hh; i += blockDim.x) {
        int c = i / Hh;
        g_WnRe[i] = ns[c] * Wre[i];
        g_WnIm[i] = ns[HM + c] * Wim[i];
    }
}

// ---------------- tf32 tensor-core GEMM: C(MxN) = A(MxK) @ B(KxN), row-major ----
// BM=128, BN=128, BK=32, 256 threads = 8 warps (2 x 4), warp tile 64x32.
// mma.sync.m16n8k8.tf32. M, K assumed multiples of 128/32; N may be ragged.
#define PADK 36

__device__ __forceinline__ unsigned f2tf(float f) {
    unsigned u;
    asm("cvt.rna.tf32.f32 %0, %1;" : "=r"(u) : "f"(f));
    return u;
}

__global__ __launch_bounds__(256, 2)
void tf32_gemm_kernel(const float* __restrict__ A, const float* __restrict__ B,
                      float* __restrict__ C, int Mdim, int Ndim, int Kdim)
{
    __shared__ unsigned As[128 * PADK];   // [m][k] k-minor
    __shared__ unsigned Bs[128 * PADK];   // [n][k] k-minor

    const int n0 = blockIdx.x * 128;
    const int m0 = blockIdx.y * 128;
    const int tid  = threadIdx.x;
    const int wid  = tid >> 5;
    const int lane = tid & 31;
    const int g  = lane >> 2;     // 0..7
    const int t4 = lane & 3;      // 0..3
    const int wm = wid & 1;       // 0..1  -> 64 rows
    const int wn = wid >> 1;      // 0..3  -> 32 cols

    float acc[4][4][4];
#pragma unroll
    for (int i = 0; i < 4; i++)
#pragma unroll
        for (int j = 0; j < 4; j++)
#pragma unroll
            for (int r = 0; r < 4; r++) acc[i][j][r] = 0.f;

    // A-load mapping: 4 iters, each thread one float4 along K
    const int a_row = tid >> 3;          // 0..31 (+32*iter)
    const int a_col = (tid & 7) * 4;
    // B-load mapping: 4 iters; idx = tid + 256*it: kg = idx>>7 (0..7), n = idx&127
    for (int k0 = 0; k0 < Kdim; k0 += 32) {
        // ---- stage A tile (128 x 32) ----
#pragma unroll
        for (int it = 0; it < 4; it++) {
            int row = a_row + it * 32;
            float4 v = *reinterpret_cast<const float4*>(
                &A[(size_t)(m0 + row) * Kdim + k0 + a_col]);
            unsigned* dst = &As[row * PADK + a_col];
            dst[0] = f2tf(v.x); dst[1] = f2tf(v.y);
            dst[2] = f2tf(v.z); dst[3] = f2tf(v.w);
        }
        // ---- stage B tile transposed: Bs[n][k] from B[k][n] ----
#pragma unroll
        for (int it = 0; it < 4; it++) {
            int idx = tid + it * 256;
            int kg = idx >> 7;            // 0..7 -> k sub-block of 4
            int nn = idx & 127;
            unsigned vv[4];
            if (n0 + nn < Ndim) {
#pragma unroll
                for (int j = 0; j < 4; j++)
                    vv[j] = f2tf(B[(size_t)(k0 + kg * 4 + j) * Ndim + n0 + nn]);
            } else {
                vv[0] = vv[1] = vv[2] = vv[3] = 0u;
            }
            unsigned* dst = &Bs[nn * PADK + kg * 4];
            dst[0] = vv[0]; dst[1] = vv[1]; dst[2] = vv[2]; dst[3] = vv[3];
        }
        __syncthreads();

        // ---- compute 32 k-steps as 4 x (m16n8k8) ----
#pragma unroll
        for (int kk = 0; kk < 32; kk += 8) {
            unsigned af[4][4], bf[4][2];
#pragma unroll
            for (int mi = 0; mi < 4; mi++) {
                int mb = wm * 64 + mi * 16;
                const unsigned* p0 = &As[(mb + g) * PADK + kk + t4];
                const unsigned* p1 = &As[(mb + 8 + g) * PADK + kk + t4];
                af[mi][0] = p0[0]; af[mi][1] = p1[0];
                af[mi][2] = p0[4]; af[mi][3] = p1[4];
            }
#pragma unroll
            for (int ni = 0; ni < 4; ni++) {
                int nb = wn * 32 + ni * 8;
                const unsigned* p = &Bs[(nb + g) * PADK + kk + t4];
                bf[ni][0] = p[0]; bf[ni][1] = p[4];
            }
#pragma unroll
            for (int mi = 0; mi < 4; mi++)
#pragma unroll
                for (int ni = 0; ni < 4; ni++) {
                    asm volatile(
                        "mma.sync.aligned.m16n8k8.row.col.f32.tf32.tf32.f32 "
                        "{%0,%1,%2,%3}, {%4,%5,%6,%7}, {%8,%9}, {%0,%1,%2,%3};\n"
                        : "+f"(acc[mi][ni][0]), "+f"(acc[mi][ni][1]),
                          "+f"(acc[mi][ni][2]), "+f"(acc[mi][ni][3])
                        : "r"(af[mi][0]), "r"(af[mi][1]),
                          "r"(af[mi][2]), "r"(af[mi][3]),
                          "r"(bf[ni][0]), "r"(bf[ni][1]));
                }
        }
        __syncthreads();
    }

    // ---- epilogue ----
#pragma unroll
    for (int mi = 0; mi < 4; mi++) {
        int r0 = m0 + wm * 64 + mi * 16 + g;
#pragma unroll
        for (int ni = 0; ni < 4; ni++) {
            int c0 = n0 + wn * 32 + ni * 8 + t4 * 2;
            if (c0 + 1 < Ndim) {
                C[(size_t)r0 * Ndim + c0]           = acc[mi][ni][0];
                C[(size_t)r0 * Ndim + c0 + 1]       = acc[mi][ni][1];
                C[(size_t)(r0 + 8) * Ndim + c0]     = acc[mi][ni][2];
                C[(size_t)(r0 + 8) * Ndim + c0 + 1] = acc[mi][ni][3];
            } else if (c0 < Ndim) {
                C[(size_t)r0 * Ndim + c0]       = acc[mi][ni][0];
                C[(size_t)(r0 + 8) * Ndim + c0] = acc[mi][ni][2];
            }
        }
    }
}

// ---------------- causal depthwise conv + split ----------------
__global__ void conv_kernel(const float* __restrict__ cw, const float* __restrict__ cb,
                            const float* __restrict__ sscale)
{
    int idx = blockIdx.x * blockDim.x + threadIdx.x;
    if (idx >= Bb * Ls * TOT) return;
    int c  = idx % TOT;
    int bl = idx / TOT;
    int l  = bl % Ls;

    float acc = cb[c];
#pragma unroll
    for (int j = 0; j < CKc; j++) {
        int ll = l - j;
        if (ll >= 0)
            acc += g_z[(size_t)(bl - j) * TOT + c] * cw[(CKc - 1 - j) * TOT + c];
    }
    if (c < Dd) {
        g_xval[(size_t)bl * Dd + c] = acc;
    } else if (c < 2 * Dd) {
        float sg = 1.f / (1.f + expf(-acc));
        g_gate[(size_t)bl * Dd + (c - Dd)] = acc * sg;   // silu
    } else {
        int k = c - 2 * Dd;
        float sr = sscale[k] * acc;
        sr = fminf(20.f, fmaxf(-20.f, sr));
        float p = expf(sr);
        float dist = (k < Kh - Aa) ? (float)(Ls - 1 - l) : (float)l;
        float tw = expf(-g_slope[k] * dist);
        g_pw[(size_t)bl * Kh + k] = p * tw;
    }
}

// ---------------- pass 1: per-(b,k,chunk) partial sums ----------------
__global__ __launch_bounds__(128)
void csum_kernel(const float* __restrict__ theta)
{
    int bi    = blockIdx.x;          // ((b*K + k)*NC + chunk)
    int chunk = bi % NC;
    int bk    = bi / NC;
    int k     = bk % Kh;
    int b     = bk / Kh;
    int c = threadIdx.x;             // channel 0..127
    int h = c >> 2, m = c & 3;
    float th = theta[(k * Hh + h) * Mm + m];
    float w0 = g_w3[0], w1 = g_w3[1], w2 = g_w3[2];

    float are = 0.f, aim = 0.f, ad = 0.f;
    size_t base = ((size_t)b * Ls + chunk * CH);
    const float* xvp = &g_xval[base * Dd + k * Hh + h];
    const float* pwp = &g_pw[base * Kh + k];
    for (int i = 0; i < CH; i++) {
        float xv  = xvp[(size_t)i * Dd];
        float pwv = pwp[(size_t)i * Kh];
        float s, co; __sincosf(xv * th, &s, &co);
        float poly = w0 + xv * (w1 - w2 * xv);
        float t = pwv * poly;
        are += t * co; aim += t * s; ad += pwv;
    }
    g_csum_re[(size_t)bi * HM + c] = are;
    g_csum_im[(size_t)bi * HM + c] = aim;
    if (c == 0) g_cden[bi] = ad;
}

// ---------------- pass 2: exclusive scan over chunks (tiny) ----------------
__global__ __launch_bounds__(128)
void cscan_kernel()
{
    int bk = blockIdx.x;     // 0..B*K-1
    int c = threadIdx.x;
    float rr = 0.f, ri = 0.f;
    for (int ch = 0; ch < NC; ch++) {
        size_t idx = ((size_t)bk * NC + ch) * HM + c;
        float tr = g_csum_re[idx], ti = g_csum_im[idx];
        g_csum_re[idx] = rr; g_csum_im[idx] = ri;
        rr += tr; ri += ti;
    }
    if (c == 0) {
        float run = 0.f;
        for (int ch = 0; ch < NC; ch++) {
            float t = g_cden[bk * NC + ch];
            g_cden[bk * NC + ch] = run;
            run += t;
        }
    }
}

// ---------------- pass 3: within-chunk scan + RMS + head matvec + gate ----------------
__global__ __launch_bounds__(128)
void main_kernel(const float* __restrict__ theta)
{
    __shared__ float WnRe_s[HM * Hh];   // 16 KB
    __shared__ float WnIm_s[HM * Hh];   // 16 KB
    __shared__ float sh_re[HM], sh_im[HM], sh_sq[HM];
    __shared__ float sh_part[HM];
    __shared__ float sh_scale;

    int bi    = blockIdx.x;
    int chunk = bi % NC;
    int bk    = bi / NC;
    int k     = bk % Kh;
    int b     = bk / Kh;
    int c = threadIdx.x;
    int h = c >> 2, m = c & 3;
    int q = c >> 5, hp = c & 31;

    for (int i = c; i < HM * Hh; i += 128) {
        WnRe_s[i] = g_WnRe[i];
        WnIm_s[i] = g_WnIm[i];
    }
    float th = theta[(k * Hh + h) * Mm + m];
    float w0 = g_w3[0], w1 = g_w3[1], w2 = g_w3[2];
    float are = g_csum_re[(size_t)bi * HM + c];
    float aim = g_csum_im[(size_t)bi * HM + c];
    float den = g_cden[bi];
    __syncthreads();

    int base_l = chunk * CH;
    for (int i = 0; i < CH; i++) {
        int l = base_l + i;
        size_t bl = (size_t)b * Ls + l;
        float xv  = g_xval[bl * Dd + k * Hh + h];
        float pwv = g_pw[bl * Kh + k];
        float s, co; __sincosf(xv * th, &s, &co);
        float poly = w0 + xv * (w1 - w2 * xv);
        float t = pwv * poly;
        are += t * co; aim += t * s; den += pwv;

        sh_re[c] = are; sh_im[c] = aim; sh_sq[c] = are * are + aim * aim;
        __syncthreads();

        float part = 0.f;
#pragma unroll
        for (int j = 0; j < 32; j++) {
            int cc = q * 32 + j;
            part += sh_re[cc] * WnRe_s[cc * Hh + hp] + sh_im[cc] * WnIm_s[cc * Hh + hp];
        }
        sh_part[c] = part;

        if (q == 0) {
            float v = sh_sq[hp] + sh_sq[hp + 32] + sh_sq[hp + 64] + sh_sq[hp + 96];
#pragma unroll
            for (int o = 16; o > 0; o >>= 1) v += __shfl_xor_sync(0xffffffffu, v, o);
            if (hp == 0) {
                float inv_den = 1.f / fmaxf(den, 1e-4f);
                float msq = inv_den * inv_den * v * (1.f / (2.f * HM)) + 1e-5f;
                sh_scale = inv_den * rsqrtf(msq);
            }
        }
        __syncthreads();

        if (c < 32) {
            float y = (sh_part[c] + sh_part[c + 32] + sh_part[c + 64] + sh_part[c + 96]) * sh_scale;
            size_t oidx = bl * Dd + k * Hh + c;
            g_yg[oidx] = y * g_gate[oidx];
        }
        __syncthreads();
    }
}

// ---------------- launcher ----------------
extern "C" void kernel_launch(void* const* d_in, const int* in_sizes, int n_in,
                              void* d_out, int out_size)
{
    const float* x             = (const float*)d_in[0];
    const float* in_proj_w     = (const float*)d_in[1];
    const float* conv_w        = (const float*)d_in[2];
    const float* conv_b        = (const float*)d_in[3];
    const float* theta         = (const float*)d_in[4];
    const float* decay_slopes  = (const float*)d_in[5];
    const float* anchor_slopes = (const float*)d_in[6];
    const float* score_scale   = (const float*)d_in[7];
    const float* deriv_logits  = (const float*)d_in[8];
    const float* norm_scale    = (const float*)d_in[9];
    const float* W_re          = (const float*)d_in[10];
    const float* W_im          = (const float*)d_in[11];
    const float* out_proj_w    = (const float*)d_in[12];
    float* out = (float*)d_out;

    float *z_p = nullptr, *yg_p = nullptr;
    cudaGetSymbolAddress((void**)&z_p, g_z);
    cudaGetSymbolAddress((void**)&yg_p, g_yg);

    prep_kernel<<<1, 256>>>(deriv_logits, norm_scale, W_re, W_im,
                            decay_slopes, anchor_slopes);

    // z = x @ in_proj_w : (4096 x 1024) @ (1024 x 2080)
    tf32_gemm_kernel<<<dim3((TOT + 127) / 128, (Bb * Ls) / 128), 256>>>(
        x, in_proj_w, z_p, Bb * Ls, TOT, Dd);

    conv_kernel<<<(Bb * Ls * TOT + 255) / 256, 256>>>(conv_w, conv_b, score_scale);

    csum_kernel<<<Bb * Kh * NC, 128>>>(theta);
    cscan_kernel<<<Bb * Kh, 128>>>();
    main_kernel<<<Bb * Kh * NC, 128>>>(theta);

    // out = yg @ out_proj_w : (4096 x 1024) @ (1024 x 1024)
    tf32_gemm_kernel<<<dim3(Dd / 128, (Bb * Ls) / 128), 256>>>(
        yg_p, out_proj_w, out, Bb * Ls, Dd, Dd);
}

// round 4
// speedup vs baseline: 2.5202x; 1.6349x over previous
#include <cuda_runtime.h>
#include <cuda_bf16.h>
#include <math.h>

// ---------------- problem constants ----------------
#define Bb   2
#define Ls   2048
#define Dd   1024
#define Kh   32
#define Hh   32
#define Mm   4
#define Aa   4
#define TOT  2080     // 2*D + K
#define CKc  4
#define HM   128      // H*M
#define CH   128      // scan chunk length
#define NC   16       // Ls / CH

// ---------------- scratch ----------------
__device__ float g_z[(size_t)Bb * Ls * TOT];
__device__ float g_xval[(size_t)Bb * Ls * Dd];
__device__ float g_gate[(size_t)Bb * Ls * Dd];
__device__ float g_pw[(size_t)Bb * Ls * Kh];
__device__ float g_yg[(size_t)Bb * Ls * Dd];
__device__ float g_num_re[(size_t)Bb * Kh * Ls * HM];   // 64 MB
__device__ float g_num_im[(size_t)Bb * Kh * Ls * HM];   // 64 MB
__device__ float g_scale[(size_t)Bb * Kh * Ls];
__device__ float g_csum_re[(size_t)Bb * Kh * NC * HM];
__device__ float g_csum_im[(size_t)Bb * Kh * NC * HM];
__device__ float g_cden[(size_t)Bb * Kh * NC];
__device__ float g_WnRe[HM * Hh];
__device__ float g_WnIm[HM * Hh];
__device__ float g_w3[3];
__device__ float g_slope[Kh];

__device__ __forceinline__ unsigned f2tf(float f) {
    unsigned u;
    asm("cvt.rna.tf32.f32 %0, %1;" : "=r"(u) : "f"(f));
    return u;
}

// ---------------- prep ----------------
__global__ void prep_kernel(const float* __restrict__ dlog,
                            const float* __restrict__ ns,
                            const float* __restrict__ Wre,
                            const float* __restrict__ Wim,
                            const float* __restrict__ ds,
                            const float* __restrict__ as_)
{
    int t = threadIdx.x;
    if (t == 0) {
        float mx = fmaxf(dlog[0], fmaxf(dlog[1], dlog[2]));
        float e0 = expf(dlog[0] - mx), e1 = expf(dlog[1] - mx), e2 = expf(dlog[2] - mx);
        float inv = 1.f / (e0 + e1 + e2);
        g_w3[0] = e0 * inv; g_w3[1] = e1 * inv; g_w3[2] = e2 * inv;
    }
    if (t < Kh) {
        float xx = (t < Kh - Aa) ? ds[t] : as_[t - (Kh - Aa)];
        g_slope[t] = (xx > 20.f) ? xx : log1pf(expf(xx));
    }
    for (int i = t; i < HM * Hh; i += blockDim.x) {
        int c = i / Hh;
        g_WnRe[i] = ns[c] * Wre[i];
        g_WnIm[i] = ns[HM + c] * Wim[i];
    }
}

// ---------------- pipelined tf32 GEMM: C(MxN)=A(MxK)@B(KxN) row-major -------
// BM=128, BN=128, BK=16, double-buffered cp.async. M multiple of 128, K of 16.
#define GPADK 20
#define GPADN 132

__global__ __launch_bounds__(256, 2)
void tf32_gemm_pipe(const float* __restrict__ A, const float* __restrict__ B,
                    float* __restrict__ C, int Mdim, int Ndim, int Kdim)
{
    __shared__ __align__(16) float As[2][128 * GPADK];
    __shared__ __align__(16) float Bs[2][16 * GPADN];

    const int n0 = blockIdx.x * 128;
    const int m0 = blockIdx.y * 128;
    const int tid  = threadIdx.x;
    const int wid  = tid >> 5;
    const int lane = tid & 31;
    const int g  = lane >> 2;
    const int t4 = lane & 3;
    const int wm = wid & 1;
    const int wn = wid >> 1;

    float acc[4][4][4];
#pragma unroll
    for (int i = 0; i < 4; i++)
#pragma unroll
        for (int j = 0; j < 4; j++)
#pragma unroll
            for (int r = 0; r < 4; r++) acc[i][j][r] = 0.f;

    auto stage = [&](int kt, int buf) {
        int k0 = kt * 16;
        // A tile: 128 x 16 = 512 float4, 2 per thread
#pragma unroll
        for (int e = 0; e < 2; e++) {
            int f4 = tid * 2 + e;
            int row = f4 >> 2, c4 = f4 & 3;
            const float* src = A + (size_t)(m0 + row) * Kdim + k0 + c4 * 4;
            unsigned dst = (unsigned)__cvta_generic_to_shared(&As[buf][row * GPADK + c4 * 4]);
            asm volatile("cp.async.cg.shared.global [%0], [%1], 16;\n" :: "r"(dst), "l"(src));
        }
        // B tile: 16 x 128 = 512 float4, 2 per thread
#pragma unroll
        for (int e = 0; e < 2; e++) {
            int f4 = tid * 2 + e;
            int kk = f4 >> 5, n4 = f4 & 31;
            int ncol = n0 + n4 * 4;
            float* dstp = &Bs[buf][kk * GPADN + n4 * 4];
            if (ncol + 3 < Ndim) {
                const float* src = B + (size_t)(k0 + kk) * Ndim + ncol;
                unsigned dst = (unsigned)__cvta_generic_to_shared(dstp);
                asm volatile("cp.async.cg.shared.global [%0], [%1], 16;\n" :: "r"(dst), "l"(src));
            } else {
#pragma unroll
                for (int j = 0; j < 4; j++)
                    dstp[j] = (ncol + j < Ndim) ? B[(size_t)(k0 + kk) * Ndim + ncol + j] : 0.f;
            }
        }
    };

    const int KT = Kdim / 16;
    stage(0, 0);
    asm volatile("cp.async.commit_group;\n" ::: "memory");

    for (int kt = 0; kt < KT; kt++) {
        int buf = kt & 1;
        if (kt + 1 < KT) {
            stage(kt + 1, buf ^ 1);
            asm volatile("cp.async.commit_group;\n" ::: "memory");
            asm volatile("cp.async.wait_group 1;\n" ::: "memory");
        } else {
            asm volatile("cp.async.wait_group 0;\n" ::: "memory");
        }
        __syncthreads();

        const float* Asb = As[buf];
        const float* Bsb = Bs[buf];
#pragma unroll
        for (int kk = 0; kk < 16; kk += 8) {
            unsigned af[4][4], bf[4][2];
#pragma unroll
            for (int mi = 0; mi < 4; mi++) {
                int mb = wm * 64 + mi * 16;
                const float* p0 = &Asb[(mb + g) * GPADK + kk + t4];
                const float* p1 = &Asb[(mb + 8 + g) * GPADK + kk + t4];
                af[mi][0] = f2tf(p0[0]); af[mi][1] = f2tf(p1[0]);
                af[mi][2] = f2tf(p0[4]); af[mi][3] = f2tf(p1[4]);
            }
#pragma unroll
            for (int ni = 0; ni < 4; ni++) {
                int nb = wn * 32 + ni * 8;
                bf[ni][0] = f2tf(Bsb[(kk + t4) * GPADN + nb + g]);
                bf[ni][1] = f2tf(Bsb[(kk + t4 + 4) * GPADN + nb + g]);
            }
#pragma unroll
            for (int mi = 0; mi < 4; mi++)
#pragma unroll
                for (int ni = 0; ni < 4; ni++) {
                    asm volatile(
                        "mma.sync.aligned.m16n8k8.row.col.f32.tf32.tf32.f32 "
                        "{%0,%1,%2,%3}, {%4,%5,%6,%7}, {%8,%9}, {%0,%1,%2,%3};\n"
                        : "+f"(acc[mi][ni][0]), "+f"(acc[mi][ni][1]),
                          "+f"(acc[mi][ni][2]), "+f"(acc[mi][ni][3])
                        : "r"(af[mi][0]), "r"(af[mi][1]),
                          "r"(af[mi][2]), "r"(af[mi][3]),
                          "r"(bf[ni][0]), "r"(bf[ni][1]));
                }
        }
        __syncthreads();
    }

#pragma unroll
    for (int mi = 0; mi < 4; mi++) {
        int r0 = m0 + wm * 64 + mi * 16 + g;
#pragma unroll
        for (int ni = 0; ni < 4; ni++) {
            int c0 = n0 + wn * 32 + ni * 8 + t4 * 2;
            if (c0 + 1 < Ndim) {
                C[(size_t)r0 * Ndim + c0]           = acc[mi][ni][0];
                C[(size_t)r0 * Ndim + c0 + 1]       = acc[mi][ni][1];
                C[(size_t)(r0 + 8) * Ndim + c0]     = acc[mi][ni][2];
                C[(size_t)(r0 + 8) * Ndim + c0 + 1] = acc[mi][ni][3];
            } else if (c0 < Ndim) {
                C[(size_t)r0 * Ndim + c0]       = acc[mi][ni][0];
                C[(size_t)(r0 + 8) * Ndim + c0] = acc[mi][ni][2];
            }
        }
    }
}

// ---------------- causal depthwise conv + split ----------------
__global__ void conv_kernel(const float* __restrict__ cw, const float* __restrict__ cb,
                            const float* __restrict__ sscale)
{
    int idx = blockIdx.x * blockDim.x + threadIdx.x;
    if (idx >= Bb * Ls * TOT) return;
    int c  = idx % TOT;
    int bl = idx / TOT;
    int l  = bl % Ls;

    float acc = cb[c];
#pragma unroll
    for (int j = 0; j < CKc; j++) {
        int ll = l - j;
        if (ll >= 0)
            acc += g_z[(size_t)(bl - j) * TOT + c] * cw[(CKc - 1 - j) * TOT + c];
    }
    if (c < Dd) {
        g_xval[(size_t)bl * Dd + c] = acc;
    } else if (c < 2 * Dd) {
        float sg = 1.f / (1.f + expf(-acc));
        g_gate[(size_t)bl * Dd + (c - Dd)] = acc * sg;
    } else {
        int k = c - 2 * Dd;
        float sr = sscale[k] * acc;
        sr = fminf(20.f, fmaxf(-20.f, sr));
        float p = expf(sr);
        float dist = (k < Kh - Aa) ? (float)(Ls - 1 - l) : (float)l;
        float tw = expf(-g_slope[k] * dist);
        g_pw[(size_t)bl * Kh + k] = p * tw;
    }
}

// ---------------- pass 1: per-(b,k,chunk) partial sums ----------------
__global__ __launch_bounds__(128)
void csum_kernel(const float* __restrict__ theta)
{
    int bi    = blockIdx.x;
    int chunk = bi % NC;
    int bk    = bi / NC;
    int k     = bk % Kh;
    int b     = bk / Kh;
    int c = threadIdx.x;
    int h = c >> 2, m = c & 3;
    float th = theta[(k * Hh + h) * Mm + m];
    float w0 = g_w3[0], w1 = g_w3[1], w2 = g_w3[2];

    float are = 0.f, aim = 0.f, ad = 0.f;
    size_t base = ((size_t)b * Ls + chunk * CH);
    const float* xvp = &g_xval[base * Dd + k * Hh + h];
    const float* pwp = &g_pw[base * Kh + k];
    for (int i0 = 0; i0 < CH; i0 += 8) {
        float xv8[8], pw8[8];
#pragma unroll
        for (int j = 0; j < 8; j++) {
            xv8[j] = xvp[(size_t)(i0 + j) * Dd];
            pw8[j] = pwp[(size_t)(i0 + j) * Kh];
        }
#pragma unroll
        for (int j = 0; j < 8; j++) {
            float xv = xv8[j], pwv = pw8[j];
            float s, co; __sincosf(xv * th, &s, &co);
            float poly = w0 + xv * (w1 - w2 * xv);
            float t = pwv * poly;
            are += t * co; aim += t * s; ad += pwv;
        }
    }
    g_csum_re[(size_t)bi * HM + c] = are;
    g_csum_im[(size_t)bi * HM + c] = aim;
    if (c == 0) g_cden[bi] = ad;
}

// ---------------- pass 2: exclusive scan over chunks ----------------
__global__ __launch_bounds__(128)
void cscan_kernel()
{
    int bk = blockIdx.x;
    int c = threadIdx.x;
    float rr = 0.f, ri = 0.f;
    for (int ch = 0; ch < NC; ch++) {
        size_t idx = ((size_t)bk * NC + ch) * HM + c;
        float tr = g_csum_re[idx], ti = g_csum_im[idx];
        g_csum_re[idx] = rr; g_csum_im[idx] = ri;
        rr += tr; ri += ti;
    }
    if (c == 0) {
        float run = 0.f;
        for (int ch = 0; ch < NC; ch++) {
            float t = g_cden[bk * NC + ch];
            g_cden[bk * NC + ch] = run;
            run += t;
        }
    }
}

// ---------------- pass 3: scan -> materialize num + per-position scale -------
__global__ __launch_bounds__(128)
void scan_kernel(const float* __restrict__ theta)
{
    __shared__ float sh_ws[32];   // [j(8)][warp(4)]

    int bi    = blockIdx.x;
    int chunk = bi % NC;
    int bk    = bi / NC;
    int k     = bk % Kh;
    int b     = bk / Kh;
    int c = threadIdx.x;
    int h = c >> 2, m = c & 3;
    int warp = c >> 5, lane = c & 31;

    float th = theta[(k * Hh + h) * Mm + m];
    float w0 = g_w3[0], w1 = g_w3[1], w2 = g_w3[2];
    float are = g_csum_re[(size_t)bi * HM + c];
    float aim = g_csum_im[(size_t)bi * HM + c];
    float den = g_cden[bi];

    int base_l = chunk * CH;
    size_t nbase = ((size_t)bk * Ls + base_l) * HM + c;
    const float* xvp = &g_xval[((size_t)b * Ls + base_l) * Dd + k * Hh + h];
    const float* pwp = &g_pw[((size_t)b * Ls + base_l) * Kh + k];

    for (int i0 = 0; i0 < CH; i0 += 8) {
        float xv8[8], pw8[8];
#pragma unroll
        for (int j = 0; j < 8; j++) {
            xv8[j] = xvp[(size_t)(i0 + j) * Dd];
            pw8[j] = pwp[(size_t)(i0 + j) * Kh];
        }
        float myden = 0.f;
#pragma unroll
        for (int j = 0; j < 8; j++) {
            float xv = xv8[j], pwv = pw8[j];
            float s, co; __sincosf(xv * th, &s, &co);
            float poly = w0 + xv * (w1 - w2 * xv);
            float t = pwv * poly;
            are += t * co; aim += t * s; den += pwv;
            g_num_re[nbase + (size_t)(i0 + j) * HM] = are;
            g_num_im[nbase + (size_t)(i0 + j) * HM] = aim;
            float sq = are * are + aim * aim;
#pragma unroll
            for (int o = 16; o > 0; o >>= 1) sq += __shfl_xor_sync(0xffffffffu, sq, o);
            if (lane == 0) sh_ws[j * 4 + warp] = sq;
            if (warp == 0 && lane == j) myden = den;
        }
        __syncthreads();
        if (warp == 0 && lane < 8) {
            float v = sh_ws[lane * 4] + sh_ws[lane * 4 + 1]
                    + sh_ws[lane * 4 + 2] + sh_ws[lane * 4 + 3];
            float inv_den = 1.f / fmaxf(myden, 1e-4f);
            float msq = inv_den * inv_den * v * (1.f / (2.f * HM)) + 1e-5f;
            g_scale[(size_t)bk * Ls + base_l + i0 + lane] = inv_den * rsqrtf(msq);
        }
        __syncthreads();
    }
}

// ---------------- head GEMM: y = scale * (num @ Wn) * gate, 3xTF32 ----------
// Block: (ltile of 128 rows, head k). 256 threads = 8 warps x 16 rows each.
#define HPADK 20
#define WPAD  260

__global__ __launch_bounds__(256)
void head_gemm_kernel()
{
    __shared__ __align__(16) float Ws[32 * WPAD];   // [hp][c 0..255]
    __shared__ __align__(16) float Ash[128 * HPADK];

    const int ltile = blockIdx.x;
    const int k     = blockIdx.y;
    const int tid  = threadIdx.x;
    const int wid  = tid >> 5;
    const int lane = tid & 31;
    const int g  = lane >> 2;
    const int t4 = lane & 3;
    const int r_base = ltile * 128;

    // stage W (shared across heads): Ws[hp][c] = Wn[c][hp]
    for (int idx = tid; idx < 256 * 32; idx += 256) {
        int cc = idx >> 5, hp = idx & 31;
        float v = (cc < HM) ? g_WnRe[cc * Hh + hp] : g_WnIm[(cc - HM) * Hh + hp];
        Ws[hp * WPAD + cc] = v;
    }

    float acc[4][4];
#pragma unroll
    for (int i = 0; i < 4; i++)
#pragma unroll
        for (int j = 0; j < 4; j++) acc[i][j] = 0.f;

    const int mb = wid * 16;

    for (int kc = 0; kc < 256; kc += 16) {
        __syncthreads();
        // stage A chunk: 128 rows x 16 c = 512 float4, 2 per thread
#pragma unroll
        for (int e = 0; e < 2; e++) {
            int f4 = tid * 2 + e;
            int row = f4 >> 2, c4 = f4 & 3;
            int r = r_base + row;
            int b = r >> 11, l = r & (Ls - 1);
            int cc = kc + c4 * 4;
            const float* src = (cc < HM)
                ? &g_num_re[((size_t)(b * Kh + k) * Ls + l) * HM + cc]
                : &g_num_im[((size_t)(b * Kh + k) * Ls + l) * HM + (cc - HM)];
            float4 v = *reinterpret_cast<const float4*>(src);
            float* dst = &Ash[row * HPADK + c4 * 4];
            dst[0] = v.x; dst[1] = v.y; dst[2] = v.z; dst[3] = v.w;
        }
        __syncthreads();

#pragma unroll
        for (int kk = 0; kk < 16; kk += 8) {
            float ar[4];
            {
                const float* p0 = &Ash[(mb + g) * HPADK + kk + t4];
                const float* p1 = &Ash[(mb + 8 + g) * HPADK + kk + t4];
                ar[0] = p0[0]; ar[1] = p1[0]; ar[2] = p0[4]; ar[3] = p1[4];
            }
            unsigned ahi[4], alo[4];
#pragma unroll
            for (int i = 0; i < 4; i++) {
                ahi[i] = f2tf(ar[i]);
                alo[i] = f2tf(ar[i] - __uint_as_float(ahi[i]));
            }
#pragma unroll
            for (int ni = 0; ni < 4; ni++) {
                int nb = ni * 8;
                float br0 = Ws[(nb + g) * WPAD + kc + kk + t4];
                float br1 = Ws[(nb + g) * WPAD + kc + kk + t4 + 4];
                unsigned bhi0 = f2tf(br0), bhi1 = f2tf(br1);
                unsigned blo0 = f2tf(br0 - __uint_as_float(bhi0));
                unsigned blo1 = f2tf(br1 - __uint_as_float(bhi1));
                asm volatile(
                    "mma.sync.aligned.m16n8k8.row.col.f32.tf32.tf32.f32 "
                    "{%0,%1,%2,%3}, {%4,%5,%6,%7}, {%8,%9}, {%0,%1,%2,%3};\n"
                    : "+f"(acc[ni][0]), "+f"(acc[ni][1]), "+f"(acc[ni][2]), "+f"(acc[ni][3])
                    : "r"(alo[0]), "r"(alo[1]), "r"(alo[2]), "r"(alo[3]),
                      "r"(bhi0), "r"(bhi1));
                asm volatile(
                    "mma.sync.aligned.m16n8k8.row.col.f32.tf32.tf32.f32 "
                    "{%0,%1,%2,%3}, {%4,%5,%6,%7}, {%8,%9}, {%0,%1,%2,%3};\n"
                    : "+f"(acc[ni][0]), "+f"(acc[ni][1]), "+f"(acc[ni][2]), "+f"(acc[ni][3])
                    : "r"(ahi[0]), "r"(ahi[1]), "r"(ahi[2]), "r"(ahi[3]),
                      "r"(blo0), "r"(blo1));
                asm volatile(
                    "mma.sync.aligned.m16n8k8.row.col.f32.tf32.tf32.f32 "
                    "{%0,%1,%2,%3}, {%4,%5,%6,%7}, {%8,%9}, {%0,%1,%2,%3};\n"
                    : "+f"(acc[ni][0]), "+f"(acc[ni][1]), "+f"(acc[ni][2]), "+f"(acc[ni][3])
                    : "r"(ahi[0]), "r"(ahi[1]), "r"(ahi[2]), "r"(ahi[3]),
                      "r"(bhi0), "r"(bhi1));
            }
        }
    }

    // epilogue: scale * gate
    int r0 = r_base + mb + g;
    int r1 = r0 + 8;
    int b0 = r0 >> 11, l0 = r0 & (Ls - 1);
    int b1 = r1 >> 11, l1 = r1 & (Ls - 1);
    float sc0 = g_scale[(size_t)(b0 * Kh + k) * Ls + l0];
    float sc1 = g_scale[(size_t)(b1 * Kh + k) * Ls + l1];
#pragma unroll
    for (int ni = 0; ni < 4; ni++) {
        int c0 = ni * 8 + t4 * 2;
        size_t i0 = (size_t)r0 * Dd + k * Hh + c0;
        size_t i1 = (size_t)r1 * Dd + k * Hh + c0;
        g_yg[i0]     = acc[ni][0] * sc0 * g_gate[i0];
        g_yg[i0 + 1] = acc[ni][1] * sc0 * g_gate[i0 + 1];
        g_yg[i1]     = acc[ni][2] * sc1 * g_gate[i1];
        g_yg[i1 + 1] = acc[ni][3] * sc1 * g_gate[i1 + 1];
    }
}

// ---------------- launcher ----------------
extern "C" void kernel_launch(void* const* d_in, const int* in_sizes, int n_in,
                              void* d_out, int out_size)
{
    const float* x             = (const float*)d_in[0];
    const float* in_proj_w     = (const float*)d_in[1];
    const float* conv_w        = (const float*)d_in[2];
    const float* conv_b        = (const float*)d_in[3];
    const float* theta         = (const float*)d_in[4];
    const float* decay_slopes  = (const float*)d_in[5];
    const float* anchor_slopes = (const float*)d_in[6];
    const float* score_scale   = (const float*)d_in[7];
    const float* deriv_logits  = (const float*)d_in[8];
    const float* norm_scale    = (const float*)d_in[9];
    const float* W_re          = (const float*)d_in[10];
    const float* W_im          = (const float*)d_in[11];
    const float* out_proj_w    = (const float*)d_in[12];
    float* out = (float*)d_out;

    float *z_p = nullptr, *yg_p = nullptr;
    cudaGetSymbolAddress((void**)&z_p, g_z);
    cudaGetSymbolAddress((void**)&yg_p, g_yg);

    prep_kernel<<<1, 256>>>(deriv_logits, norm_scale, W_re, W_im,
                            decay_slopes, anchor_slopes);

    // z = x @ in_proj_w : (4096 x 1024) @ (1024 x 2080)
    tf32_gemm_pipe<<<dim3((TOT + 127) / 128, (Bb * Ls) / 128), 256>>>(
        x, in_proj_w, z_p, Bb * Ls, TOT, Dd);

    conv_kernel<<<(Bb * Ls * TOT + 255) / 256, 256>>>(conv_w, conv_b, score_scale);

    csum_kernel<<<Bb * Kh * NC, 128>>>(theta);
    cscan_kernel<<<Bb * Kh, 128>>>();
    scan_kernel<<<Bb * Kh * NC, 128>>>(theta);
    head_gemm_kernel<<<dim3((Bb * Ls) / 128, Kh), 256>>>();

    // out = yg @ out_proj_w : (4096 x 1024) @ (1024 x 1024)
    tf32_gemm_pipe<<<dim3(Dd / 128, (Bb * Ls) / 128), 256>>>(
        yg_p, out_proj_w, out, Bb * Ls, Dd, Dd);
}